// round 11
// baseline (speedup 1.0000x reference)
#include <cuda_runtime.h>
#include <cuda_bf16.h>
#include <cstdint>
#include <math.h>

// ===========================================================================
// Shapes: B=4, S=1024, H=16, D=256, HID=4096, TOK=4096
// All GEMMs: NT bf16 mma.sync (m16n8k16) with hi/lo operand split:
//   C = Ah*Bh^T + Ah*Bl^T + Al*Bh^T
// R11: R10 GEMM core (proven, untouched) +
//   - QKV epilogue fusion (pvmode=2): RoPE + hi/lo split + V transpose are
//     done in the QKV GEMM epilogue; g_qkv, k_ropec, k_vt deleted.
//   - softmax stores capped at diagonal block end (PV K-cap never reads past).
// ===========================================================================

// ---------------- scratch ---------------------------------------------------
static __device__ float g_scores[(size_t)64 * 1024 * 1024];

static __device__ __nv_bfloat16 g_Xh[(size_t)4096 * 4096],  g_Xl[(size_t)4096 * 4096];
static __device__ __nv_bfloat16 g_WqTh[(size_t)12288 * 4096], g_WqTl[(size_t)12288 * 4096];
static __device__ __nv_bfloat16 g_WoTh[(size_t)4096 * 4096],  g_WoTl[(size_t)4096 * 4096];
static __device__ __nv_bfloat16 g_Qh[(size_t)64 * 1024 * 256], g_Ql[(size_t)64 * 1024 * 256];
static __device__ __nv_bfloat16 g_Kh[(size_t)64 * 1024 * 256], g_Kl[(size_t)64 * 1024 * 256];
static __device__ __nv_bfloat16 g_Vth[(size_t)64 * 256 * 1024], g_Vtl[(size_t)64 * 256 * 1024];
static __device__ __nv_bfloat16 g_Ph[(size_t)64 * 1024 * 1024], g_Pl[(size_t)64 * 1024 * 1024];
static __device__ __nv_bfloat16 g_Ah[(size_t)4096 * 4096],  g_Al[(size_t)4096 * 4096];

// ---------------- PTX helpers ----------------------------------------------
__device__ __forceinline__ uint32_t smem_u32(const void* p) {
    uint32_t a;
    asm("{ .reg .u64 t; cvta.to.shared.u64 t, %1; cvt.u32.u64 %0, t; }"
        : "=r"(a) : "l"(p));
    return a;
}
#define CPA16(d, s) \
    asm volatile("cp.async.cg.shared.global [%0], [%1], 16;" :: "r"(d), "l"(s))
#define CP_COMMIT() asm volatile("cp.async.commit_group;" ::: "memory")
#define CP_WAIT(n)  asm volatile("cp.async.wait_group %0;" :: "n"(n) : "memory")

__device__ __forceinline__ void ldsm4(uint32_t* r, uint32_t addr) {
    asm volatile("ldmatrix.sync.aligned.m8n8.x4.shared.b16 {%0,%1,%2,%3}, [%4];"
                 : "=r"(r[0]), "=r"(r[1]), "=r"(r[2]), "=r"(r[3]) : "r"(addr));
}
__device__ __forceinline__ void mma16816(float* d, const uint32_t* a,
                                         const uint32_t b0, const uint32_t b1) {
    asm volatile(
        "mma.sync.aligned.m16n8k16.row.col.f32.bf16.bf16.f32 "
        "{%0,%1,%2,%3}, {%4,%5,%6,%7}, {%8,%9}, {%0,%1,%2,%3};"
        : "+f"(d[0]), "+f"(d[1]), "+f"(d[2]), "+f"(d[3])
        : "r"(a[0]), "r"(a[1]), "r"(a[2]), "r"(a[3]), "r"(b0), "r"(b1));
}
__device__ __forceinline__ void split_bf16(float v, __nv_bfloat16& h, __nv_bfloat16& l) {
    h = __float2bfloat16(v);
    l = __float2bfloat16(v - __bfloat162float(h));
}

// ---------------- SMEM layout ----------------------------------------------
// Stage = Ah(128x32 @80B rows) Al Bh Bl, each 10240B -> 40960B; 2 stages.
#define ROWB   80
#define BUFB   10240
#define STAGEB 40960
#define SMEMSZ (2 * STAGEB)
#define PITCH  130   // fp32 staging pitch for the fused QKV epilogue

// ===========================================================================
// bf16x2-split NT GEMM: C[M,N] = alpha * (A[M,K] @ B[N,K]^T)
// CTA 128x128, BK=32, 256 thr = 8 warps (4M x 2N), warp tile 32x64.
// causal=1: skip fully-masked upper tiles (scores). causal=2: PV K-cap.
// pvmode=0: fp32 C.  pvmode=1: bf16 hi/lo to Oh/Ol at attn layout.
// pvmode=2: fused QKV epilogue (RoPE q/k + split, V transpose); Oh/Ol = Q.
// ===========================================================================
__global__ __launch_bounds__(256, 2)
void k_mma(const __nv_bfloat16* __restrict__ Ahp, const __nv_bfloat16* __restrict__ Alp,
           const __nv_bfloat16* __restrict__ Bhp, const __nv_bfloat16* __restrict__ Blp,
           float* __restrict__ Cp,
           __nv_bfloat16* __restrict__ Oh, __nv_bfloat16* __restrict__ Ol,
           int K, int lda, int ldb, int ldc,
           long strideA, long strideB, long strideC,
           float alpha, int causal, int pvmode,
           const int* __restrict__ posp,
           __nv_bfloat16* __restrict__ Kh_, __nv_bfloat16* __restrict__ Kl_,
           __nv_bfloat16* __restrict__ Vh_, __nv_bfloat16* __restrict__ Vl_)
{
    const int m0 = blockIdx.y * 128;
    const int n0 = blockIdx.x * 128;
    if (causal == 1 && n0 > m0 + 127) return;
    if (causal == 2) K = min(K, m0 + 128);   // P lower-triangular K-cap

    const int z = blockIdx.z;
    const __nv_bfloat16* Ah = Ahp + (size_t)z * strideA + (size_t)m0 * lda;
    const __nv_bfloat16* Al = Alp + (size_t)z * strideA + (size_t)m0 * lda;
    const __nv_bfloat16* Bh = Bhp + (size_t)z * strideB + (size_t)n0 * ldb;
    const __nv_bfloat16* Bl = Blp + (size_t)z * strideB + (size_t)n0 * ldb;

    extern __shared__ char smem[];
    const uint32_t sbase = smem_u32(smem);
    const int tid = threadIdx.x;
    const int wid = tid >> 5;
    const int lane = tid & 31;
    const int wm = wid & 3;
    const int wn = wid >> 2;

    const int lr = tid >> 2;
    const int lc = tid & 3;
    const uint32_t ldst = (uint32_t)lr * ROWB + lc * 16;
    const int lcol = lc * 8;

    const uint32_t a_row = (uint32_t)(wm * 32 + (lane & 15));
    const uint32_t a_kb  = (uint32_t)((lane >> 4) * 16);
    const uint32_t b_row = (uint32_t)(wn * 64 + (lane & 7) + ((lane >> 4) << 3));
    const uint32_t b_kb  = (uint32_t)(((lane >> 3) & 1) * 16);

    float acc[2][8][4];
    #pragma unroll
    for (int i = 0; i < 2; i++)
        #pragma unroll
        for (int j = 0; j < 8; j++)
            #pragma unroll
            for (int q = 0; q < 4; q++) acc[i][j][q] = 0.0f;

    const int nK = K >> 5;

    // prologue: stage 0
    {
        #pragma unroll
        for (int i = 0; i < 2; i++) {
            const int r = lr + i * 64;
            const uint32_t d = sbase + (uint32_t)i * 64 * ROWB + ldst;
            CPA16(d,            Ah + (size_t)r * lda + lcol);
            CPA16(d + BUFB,     Al + (size_t)r * lda + lcol);
            CPA16(d + 2 * BUFB, Bh + (size_t)r * ldb + lcol);
            CPA16(d + 3 * BUFB, Bl + (size_t)r * ldb + lcol);
        }
        CP_COMMIT();
    }

    for (int it = 0; it < nK; it++) {
        if (it + 1 < nK) {
            const int k0 = (it + 1) << 5;
            const uint32_t sb = sbase + ((it + 1) & 1) * STAGEB;
            #pragma unroll
            for (int i = 0; i < 2; i++) {
                const int r = lr + i * 64;
                const uint32_t d = sb + (uint32_t)i * 64 * ROWB + ldst;
                CPA16(d,            Ah + (size_t)r * lda + k0 + lcol);
                CPA16(d + BUFB,     Al + (size_t)r * lda + k0 + lcol);
                CPA16(d + 2 * BUFB, Bh + (size_t)r * ldb + k0 + lcol);
                CPA16(d + 3 * BUFB, Bl + (size_t)r * ldb + k0 + lcol);
            }
            CP_COMMIT();
            CP_WAIT(1);
        } else {
            CP_WAIT(0);
        }
        __syncthreads();

        const uint32_t sA = sbase + (it & 1) * STAGEB;
        const uint32_t sB = sA + 2 * BUFB;

        #pragma unroll
        for (int ks = 0; ks < 2; ks++) {
            const uint32_t kb = (uint32_t)(ks * 32);
            uint32_t a_h[2][4], a_l[2][4];
            #pragma unroll
            for (int mt = 0; mt < 2; mt++) {
                const uint32_t ao = (a_row + mt * 16) * ROWB + kb + a_kb;
                ldsm4(a_h[mt], sA + ao);
                ldsm4(a_l[mt], sA + BUFB + ao);
            }
            #pragma unroll
            for (int nt2 = 0; nt2 < 4; nt2++) {
                const uint32_t bo = (b_row + nt2 * 16) * ROWB + kb + b_kb;
                uint32_t b_h[4], b_l[4];
                ldsm4(b_h, sB + bo);
                ldsm4(b_l, sB + BUFB + bo);
                #pragma unroll
                for (int mt = 0; mt < 2; mt++) {
                    #pragma unroll
                    for (int hf = 0; hf < 2; hf++) {
                        float* d = acc[mt][nt2 * 2 + hf];
                        mma16816(d, a_h[mt], b_h[hf * 2], b_h[hf * 2 + 1]);
                        mma16816(d, a_h[mt], b_l[hf * 2], b_l[hf * 2 + 1]);
                        mma16816(d, a_l[mt], b_h[hf * 2], b_h[hf * 2 + 1]);
                    }
                }
            }
        }
        __syncthreads();
    }

    // ---- epilogue ----
    const int rbase = wm * 32 + (lane >> 2);
    const int cbase = wn * 64 + (lane & 3) * 2;
    if (pvmode == 1) {
        const size_t orow0 = (size_t)(z >> 4) * 1024 + m0;
        const int ocol0 = (z & 15) * 256 + n0;
        #pragma unroll
        for (int mt = 0; mt < 2; mt++) {
            #pragma unroll
            for (int nt = 0; nt < 8; nt++) {
                #pragma unroll
                for (int hrow = 0; hrow < 2; hrow++) {
                    const size_t r = orow0 + rbase + mt * 16 + hrow * 8;
                    const int cc = ocol0 + cbase + nt * 8;
                    __nv_bfloat16 h[2], l[2];
                    split_bf16(acc[mt][nt][hrow * 2]     * alpha, h[0], l[0]);
                    split_bf16(acc[mt][nt][hrow * 2 + 1] * alpha, h[1], l[1]);
                    *(uint32_t*)(Oh + r * 4096 + cc) = *(const uint32_t*)h;
                    *(uint32_t*)(Ol + r * 4096 + cc) = *(const uint32_t*)l;
                }
            }
        }
    } else if (pvmode == 2) {
        // ---- fused QKV epilogue: stage fp32 tile, then RoPE/split/transpose
        float* st = (float*)smem;   // 128 x 128 fp32, pitch PITCH (=66560B)
        #pragma unroll
        for (int mt = 0; mt < 2; mt++)
            #pragma unroll
            for (int nt = 0; nt < 8; nt++)
                #pragma unroll
                for (int hrow = 0; hrow < 2; hrow++) {
                    const int r = rbase + mt * 16 + hrow * 8;
                    const int cc = cbase + nt * 8;
                    st[r * PITCH + cc]     = acc[mt][nt][hrow * 2];
                    st[r * PITCH + cc + 1] = acc[mt][nt][hrow * 2 + 1];
                }
        __syncthreads();

        const int sec  = n0 >> 12;           // 0=q, 1=k, 2=v
        const int head = (n0 & 4095) >> 8;   // 0..15
        const int half = (n0 >> 7) & 1;      // 0 or 1 within head

        if (sec < 2) {
            __nv_bfloat16* Dh = sec ? Kh_ : Oh;
            __nv_bfloat16* Dl = sec ? Kl_ : Ol;
            const int row = tid >> 1;        // local row 0..127
            const int cch = (tid & 1) * 64;  // col chunk
            const int tok = m0 + row;
            const size_t base =
                (((size_t)((tok >> 10) * 16 + head) * 1024) + (tok & 1023)) * 256
                + half * 128;
            const float* srow = st + row * PITCH;
            if (half == 0) {
                // rotary block: pairs (j, j+64), j in 0..63
                const float pos = (float)posp[tok];
                #pragma unroll 4
                for (int i = 0; i < 64; i++) {
                    const int d = cch + i;
                    const int j = d & 63;
                    const float inv =
                        exp2f(-13.287712379549449f * (float)j * (1.0f / 64.0f));
                    float sn, cs; sincosf(pos * inv, &sn, &cs);
                    const float x1 = srow[j];
                    const float x2 = srow[j + 64];
                    const float v = (d < 64) ? (x1 * cs - x2 * sn)
                                             : (x2 * cs + x1 * sn);
                    __nv_bfloat16 hh, ll; split_bf16(v, hh, ll);
                    Dh[base + d] = hh; Dl[base + d] = ll;
                }
            } else {
                #pragma unroll 8
                for (int i = 0; i < 64; i++) {
                    const int d = cch + i;
                    __nv_bfloat16 hh, ll; split_bf16(srow[d], hh, ll);
                    Dh[base + d] = hh; Dl[base + d] = ll;
                }
            }
        } else {
            // v section: transpose to Vt[bh][d][s]; rows are tokens (same b)
            const int dloc = tid >> 1;        // local d 0..127
            const int sc = (tid & 1) * 64;    // s chunk
            const int bh = (m0 >> 10) * 16 + head;
            const int d = half * 128 + dloc;
            const size_t base =
                ((size_t)bh * 256 + d) * 1024 + (m0 & 1023) + sc;
            #pragma unroll 8
            for (int i = 0; i < 64; i++) {
                __nv_bfloat16 hh, ll;
                split_bf16(st[(sc + i) * PITCH + dloc], hh, ll);
                Vh_[base + i] = hh; Vl_[base + i] = ll;
            }
        }
    } else {
        float* C = Cp + (size_t)z * strideC;
        #pragma unroll
        for (int mt = 0; mt < 2; mt++) {
            #pragma unroll
            for (int nt = 0; nt < 8; nt++) {
                const int r0 = m0 + rbase + mt * 16;
                const int cc = n0 + cbase + nt * 8;
                float2 v0 = { acc[mt][nt][0] * alpha, acc[mt][nt][1] * alpha };
                float2 v1 = { acc[mt][nt][2] * alpha, acc[mt][nt][3] * alpha };
                *(float2*)(C + (size_t)r0 * ldc + cc)       = v0;
                *(float2*)(C + (size_t)(r0 + 8) * ldc + cc) = v1;
            }
        }
    }
}

// ===========================================================================
// Conversion / elementwise kernels
// ===========================================================================
__global__ void k_cvt(const float* __restrict__ x,
                      __nv_bfloat16* __restrict__ hi, __nv_bfloat16* __restrict__ lo)
{
    const size_t i = (size_t)blockIdx.x * 256 + threadIdx.x;
    const float4 v = ((const float4*)x)[i];
    __nv_bfloat16 h[4], l[4];
    split_bf16(v.x, h[0], l[0]); split_bf16(v.y, h[1], l[1]);
    split_bf16(v.z, h[2], l[2]); split_bf16(v.w, h[3], l[3]);
    ((uint2*)hi)[i] = *(const uint2*)h;
    ((uint2*)lo)[i] = *(const uint2*)l;
}

__global__ void k_cvt_t(const float* __restrict__ w,
                        __nv_bfloat16* __restrict__ hi, __nv_bfloat16* __restrict__ lo,
                        int R, int Cc)
{
    __shared__ float t[32][33];
    const int c0 = blockIdx.x * 32, r0 = blockIdx.y * 32;
    const int tx = threadIdx.x, ty = threadIdx.y;
    #pragma unroll
    for (int i = ty; i < 32; i += 8)
        t[i][tx] = w[(size_t)(r0 + i) * Cc + c0 + tx];
    __syncthreads();
    #pragma unroll
    for (int i = ty; i < 32; i += 8) {
        const float v = t[tx][i];
        __nv_bfloat16 h, l; split_bf16(v, h, l);
        const size_t o = (size_t)(c0 + i) * R + r0 + tx;
        hi[o] = h; lo[o] = l;
    }
}

__global__ void k_softmax_cvt(const float* __restrict__ s,
                              __nv_bfloat16* __restrict__ Ph, __nv_bfloat16* __restrict__ Pl)
{
    __shared__ float redm[8], reds[8];
    const int row = blockIdx.x & 1023;
    const float* p = s + (size_t)blockIdx.x * 1024;
    const int tid = threadIdx.x;
    const int j0 = tid * 4;

    float4 v = ((const float4*)p)[tid];
    if (j0 + 0 > row) v.x = -1e30f;
    if (j0 + 1 > row) v.y = -1e30f;
    if (j0 + 2 > row) v.z = -1e30f;
    if (j0 + 3 > row) v.w = -1e30f;

    float m = fmaxf(fmaxf(v.x, v.y), fmaxf(v.z, v.w));
    #pragma unroll
    for (int o = 16; o; o >>= 1) m = fmaxf(m, __shfl_xor_sync(~0u, m, o));
    if ((tid & 31) == 0) redm[tid >> 5] = m;
    __syncthreads();
    m = redm[0];
    #pragma unroll
    for (int i = 1; i < 8; i++) m = fmaxf(m, redm[i]);

    const float e0 = __expf(v.x - m), e1 = __expf(v.y - m);
    const float e2 = __expf(v.z - m), e3 = __expf(v.w - m);
    float sl = (e0 + e1) + (e2 + e3);
    #pragma unroll
    for (int o = 16; o; o >>= 1) sl += __shfl_xor_sync(~0u, sl, o);
    if ((tid & 31) == 0) reds[tid >> 5] = sl;
    __syncthreads();
    float tot = reds[0];
    #pragma unroll
    for (int i = 1; i < 8; i++) tot += reds[i];

    // PV reads only cols < (row|127)+1 (K-cap): skip dead stores past it.
    if (j0 <= (row | 127)) {
        const float inv = 1.0f / tot;
        __nv_bfloat16 h[4], l[4];
        split_bf16(e0 * inv, h[0], l[0]); split_bf16(e1 * inv, h[1], l[1]);
        split_bf16(e2 * inv, h[2], l[2]); split_bf16(e3 * inv, h[3], l[3]);
        const size_t o = (size_t)blockIdx.x * 256 + tid;
        ((uint2*)Ph)[o] = *(const uint2*)h;
        ((uint2*)Pl)[o] = *(const uint2*)l;
    }
}

// ===========================================================================
// Launch
// ===========================================================================
extern "C" void kernel_launch(void* const* d_in, const int* in_sizes, int n_in,
                              void* d_out, int out_size)
{
    const int*   pos  = (const int*)d_in[0];
    const float* hid  = (const float*)d_in[1];
    const float* wqkv = (const float*)d_in[2];
    const float* wout = (const float*)d_in[3];
    float* out = (float*)d_out;

    float* scores;
    __nv_bfloat16 *Xh, *Xl, *WqTh, *WqTl, *WoTh, *WoTl;
    __nv_bfloat16 *Qh, *Ql, *Kh, *Kl, *Vth, *Vtl, *Ph, *Pl, *Ah, *Al;
    cudaGetSymbolAddress((void**)&scores, g_scores);
    cudaGetSymbolAddress((void**)&Xh, g_Xh);   cudaGetSymbolAddress((void**)&Xl, g_Xl);
    cudaGetSymbolAddress((void**)&WqTh, g_WqTh); cudaGetSymbolAddress((void**)&WqTl, g_WqTl);
    cudaGetSymbolAddress((void**)&WoTh, g_WoTh); cudaGetSymbolAddress((void**)&WoTl, g_WoTl);
    cudaGetSymbolAddress((void**)&Qh, g_Qh);   cudaGetSymbolAddress((void**)&Ql, g_Ql);
    cudaGetSymbolAddress((void**)&Kh, g_Kh);   cudaGetSymbolAddress((void**)&Kl, g_Kl);
    cudaGetSymbolAddress((void**)&Vth, g_Vth); cudaGetSymbolAddress((void**)&Vtl, g_Vtl);
    cudaGetSymbolAddress((void**)&Ph, g_Ph);   cudaGetSymbolAddress((void**)&Pl, g_Pl);
    cudaGetSymbolAddress((void**)&Ah, g_Ah);   cudaGetSymbolAddress((void**)&Al, g_Al);

    cudaFuncSetAttribute(k_mma, cudaFuncAttributeMaxDynamicSharedMemorySize, SMEMSZ);

    // 1) operand conversions
    k_cvt<<<16384, 256>>>(hid, Xh, Xl);
    k_cvt_t<<<dim3(12288 / 32, 4096 / 32), dim3(32, 8)>>>(wqkv, WqTh, WqTl, 4096, 12288);
    k_cvt_t<<<dim3(4096 / 32, 4096 / 32), dim3(32, 8)>>>(wout, WoTh, WoTl, 4096, 4096);

    // 2) qkv = X @ Wqkv, fused epilogue: RoPE(q,k)+split -> Q/K, transpose -> Vt
    k_mma<<<dim3(96, 32, 1), 256, SMEMSZ>>>(Xh, Xl, WqTh, WqTl, nullptr, Qh, Ql,
        4096, 4096, 4096, 0, 0, 0, 0, 1.0f, 0, 2, pos, Kh, Kl, Vth, Vtl);

    // 3) scores = scale * Q @ K^T, causal tile skip
    k_mma<<<dim3(8, 8, 64), 256, SMEMSZ>>>(Qh, Ql, Kh, Kl, scores, nullptr, nullptr,
        256, 256, 256, 1024, 1024 * 256, 1024 * 256, 1024 * 1024, 0.0625f, 1, 0,
        nullptr, nullptr, nullptr, nullptr, nullptr);

    // 4) softmax -> bf16 hi/lo probs (stores capped at diagonal block end)
    k_softmax_cvt<<<64 * 1024, 256>>>(scores, Ph, Pl);

    // 5) attn = P @ V, causal K-cap, epilogue emits bf16 hi/lo (Ah/Al)
    k_mma<<<dim3(2, 8, 64), 256, SMEMSZ>>>(Ph, Pl, Vth, Vtl, nullptr, Ah, Al,
        1024, 1024, 1024, 4096, 1024 * 1024, 256 * 1024, 0, 1.0f, 2, 1,
        nullptr, nullptr, nullptr, nullptr, nullptr);

    // 6) out = attn @ Wout
    k_mma<<<dim3(32, 32, 1), 256, SMEMSZ>>>(Ah, Al, WoTh, WoTl, out, nullptr, nullptr,
        4096, 4096, 4096, 4096, 0, 0, 0, 1.0f, 0, 0,
        nullptr, nullptr, nullptr, nullptr, nullptr);
}

// round 13
// speedup vs baseline: 1.1515x; 1.1515x over previous
#include <cuda_runtime.h>
#include <cuda_bf16.h>
#include <cstdint>
#include <math.h>

// ===========================================================================
// Shapes: B=4, S=1024, H=16, D=256, HID=4096, TOK=4096
// All GEMMs: NT bf16 mma.sync (m16n8k16) with hi/lo operand split:
//   C = Ah*Bh^T + Ah*Bl^T + Al*Bh^T
// R12: R10 base (proven 4955us) +
//   - term-major MMA interleave: same-accumulator RAW distance 1 -> 4 MMAs
//   - softmax read+store caps at causal boundary (lossless)
// ===========================================================================

// ---------------- scratch ---------------------------------------------------
static __device__ float g_qkv[(size_t)4096 * 12288];
static __device__ float g_scores[(size_t)64 * 1024 * 1024];

static __device__ __nv_bfloat16 g_Xh[(size_t)4096 * 4096],  g_Xl[(size_t)4096 * 4096];
static __device__ __nv_bfloat16 g_WqTh[(size_t)12288 * 4096], g_WqTl[(size_t)12288 * 4096];
static __device__ __nv_bfloat16 g_WoTh[(size_t)4096 * 4096],  g_WoTl[(size_t)4096 * 4096];
static __device__ __nv_bfloat16 g_Qh[(size_t)64 * 1024 * 256], g_Ql[(size_t)64 * 1024 * 256];
static __device__ __nv_bfloat16 g_Kh[(size_t)64 * 1024 * 256], g_Kl[(size_t)64 * 1024 * 256];
static __device__ __nv_bfloat16 g_Vth[(size_t)64 * 256 * 1024], g_Vtl[(size_t)64 * 256 * 1024];
static __device__ __nv_bfloat16 g_Ph[(size_t)64 * 1024 * 1024], g_Pl[(size_t)64 * 1024 * 1024];
static __device__ __nv_bfloat16 g_Ah[(size_t)4096 * 4096],  g_Al[(size_t)4096 * 4096];

// ---------------- PTX helpers ----------------------------------------------
__device__ __forceinline__ uint32_t smem_u32(const void* p) {
    uint32_t a;
    asm("{ .reg .u64 t; cvta.to.shared.u64 t, %1; cvt.u32.u64 %0, t; }"
        : "=r"(a) : "l"(p));
    return a;
}
#define CPA16(d, s) \
    asm volatile("cp.async.cg.shared.global [%0], [%1], 16;" :: "r"(d), "l"(s))
#define CP_COMMIT() asm volatile("cp.async.commit_group;" ::: "memory")
#define CP_WAIT(n)  asm volatile("cp.async.wait_group %0;" :: "n"(n) : "memory")

__device__ __forceinline__ void ldsm4(uint32_t* r, uint32_t addr) {
    asm volatile("ldmatrix.sync.aligned.m8n8.x4.shared.b16 {%0,%1,%2,%3}, [%4];"
                 : "=r"(r[0]), "=r"(r[1]), "=r"(r[2]), "=r"(r[3]) : "r"(addr));
}
__device__ __forceinline__ void mma16816(float* d, const uint32_t* a,
                                         const uint32_t b0, const uint32_t b1) {
    asm volatile(
        "mma.sync.aligned.m16n8k16.row.col.f32.bf16.bf16.f32 "
        "{%0,%1,%2,%3}, {%4,%5,%6,%7}, {%8,%9}, {%0,%1,%2,%3};"
        : "+f"(d[0]), "+f"(d[1]), "+f"(d[2]), "+f"(d[3])
        : "r"(a[0]), "r"(a[1]), "r"(a[2]), "r"(a[3]), "r"(b0), "r"(b1));
}
__device__ __forceinline__ void split_bf16(float v, __nv_bfloat16& h, __nv_bfloat16& l) {
    h = __float2bfloat16(v);
    l = __float2bfloat16(v - __bfloat162float(h));
}

// ---------------- SMEM layout ----------------------------------------------
// Stage = Ah(128x32 @80B rows) Al Bh Bl, each 10240B -> 40960B; 2 stages.
#define ROWB   80
#define BUFB   10240
#define STAGEB 40960
#define SMEMSZ (2 * STAGEB)

// ===========================================================================
// bf16x2-split NT GEMM: C[M,N] = alpha * (A[M,K] @ B[N,K]^T)
// CTA 128x128, BK=32, 256 thr = 8 warps (4M x 2N), warp tile 32x64.
// causal=1: skip fully-masked upper tiles (scores). causal=2: PV K-cap.
// pvmode=1: epilogue writes bf16 hi/lo to Oh/Ol at attn layout.
// ===========================================================================
__global__ __launch_bounds__(256, 2)
void k_mma(const __nv_bfloat16* __restrict__ Ahp, const __nv_bfloat16* __restrict__ Alp,
           const __nv_bfloat16* __restrict__ Bhp, const __nv_bfloat16* __restrict__ Blp,
           float* __restrict__ Cp,
           __nv_bfloat16* __restrict__ Oh, __nv_bfloat16* __restrict__ Ol,
           int K, int lda, int ldb, int ldc,
           long strideA, long strideB, long strideC,
           float alpha, int causal, int pvmode)
{
    const int m0 = blockIdx.y * 128;
    const int n0 = blockIdx.x * 128;
    if (causal == 1 && n0 > m0 + 127) return;
    if (causal == 2) K = min(K, m0 + 128);   // P lower-triangular K-cap

    const int z = blockIdx.z;
    const __nv_bfloat16* Ah = Ahp + (size_t)z * strideA + (size_t)m0 * lda;
    const __nv_bfloat16* Al = Alp + (size_t)z * strideA + (size_t)m0 * lda;
    const __nv_bfloat16* Bh = Bhp + (size_t)z * strideB + (size_t)n0 * ldb;
    const __nv_bfloat16* Bl = Blp + (size_t)z * strideB + (size_t)n0 * ldb;

    extern __shared__ char smem[];
    const uint32_t sbase = smem_u32(smem);
    const int tid = threadIdx.x;
    const int wid = tid >> 5;
    const int lane = tid & 31;
    const int wm = wid & 3;
    const int wn = wid >> 2;

    const int lr = tid >> 2;
    const int lc = tid & 3;
    const uint32_t ldst = (uint32_t)lr * ROWB + lc * 16;
    const int lcol = lc * 8;

    const uint32_t a_row = (uint32_t)(wm * 32 + (lane & 15));
    const uint32_t a_kb  = (uint32_t)((lane >> 4) * 16);
    const uint32_t b_row = (uint32_t)(wn * 64 + (lane & 7) + ((lane >> 4) << 3));
    const uint32_t b_kb  = (uint32_t)(((lane >> 3) & 1) * 16);

    float acc[2][8][4];
    #pragma unroll
    for (int i = 0; i < 2; i++)
        #pragma unroll
        for (int j = 0; j < 8; j++)
            #pragma unroll
            for (int q = 0; q < 4; q++) acc[i][j][q] = 0.0f;

    const int nK = K >> 5;

    // prologue: stage 0
    {
        #pragma unroll
        for (int i = 0; i < 2; i++) {
            const int r = lr + i * 64;
            const uint32_t d = sbase + (uint32_t)i * 64 * ROWB + ldst;
            CPA16(d,            Ah + (size_t)r * lda + lcol);
            CPA16(d + BUFB,     Al + (size_t)r * lda + lcol);
            CPA16(d + 2 * BUFB, Bh + (size_t)r * ldb + lcol);
            CPA16(d + 3 * BUFB, Bl + (size_t)r * ldb + lcol);
        }
        CP_COMMIT();
    }

    for (int it = 0; it < nK; it++) {
        if (it + 1 < nK) {
            const int k0 = (it + 1) << 5;
            const uint32_t sb = sbase + ((it + 1) & 1) * STAGEB;
            #pragma unroll
            for (int i = 0; i < 2; i++) {
                const int r = lr + i * 64;
                const uint32_t d = sb + (uint32_t)i * 64 * ROWB + ldst;
                CPA16(d,            Ah + (size_t)r * lda + k0 + lcol);
                CPA16(d + BUFB,     Al + (size_t)r * lda + k0 + lcol);
                CPA16(d + 2 * BUFB, Bh + (size_t)r * ldb + k0 + lcol);
                CPA16(d + 3 * BUFB, Bl + (size_t)r * ldb + k0 + lcol);
            }
            CP_COMMIT();
            CP_WAIT(1);
        } else {
            CP_WAIT(0);
        }
        __syncthreads();

        const uint32_t sA = sbase + (it & 1) * STAGEB;
        const uint32_t sB = sA + 2 * BUFB;

        #pragma unroll
        for (int ks = 0; ks < 2; ks++) {
            const uint32_t kb = (uint32_t)(ks * 32);
            uint32_t a_h[2][4], a_l[2][4];
            #pragma unroll
            for (int mt = 0; mt < 2; mt++) {
                const uint32_t ao = (a_row + mt * 16) * ROWB + kb + a_kb;
                ldsm4(a_h[mt], sA + ao);
                ldsm4(a_l[mt], sA + BUFB + ao);
            }
            #pragma unroll
            for (int nt2 = 0; nt2 < 4; nt2++) {
                const uint32_t bo = (b_row + nt2 * 16) * ROWB + kb + b_kb;
                uint32_t b_h[4], b_l[4];
                ldsm4(b_h, sB + bo);
                ldsm4(b_l, sB + BUFB + bo);
                // term-major interleave: consecutive MMAs hit DISTINCT
                // accumulators; same-acc RAW distance = 4 MMAs (covers HMMA
                // latency). Per-acc term order (hh, hl, lh) preserved ->
                // bit-identical numerics vs R10.
                #pragma unroll
                for (int mt = 0; mt < 2; mt++)
                    #pragma unroll
                    for (int hf = 0; hf < 2; hf++)
                        mma16816(acc[mt][nt2 * 2 + hf], a_h[mt],
                                 b_h[hf * 2], b_h[hf * 2 + 1]);
                #pragma unroll
                for (int mt = 0; mt < 2; mt++)
                    #pragma unroll
                    for (int hf = 0; hf < 2; hf++)
                        mma16816(acc[mt][nt2 * 2 + hf], a_h[mt],
                                 b_l[hf * 2], b_l[hf * 2 + 1]);
                #pragma unroll
                for (int mt = 0; mt < 2; mt++)
                    #pragma unroll
                    for (int hf = 0; hf < 2; hf++)
                        mma16816(acc[mt][nt2 * 2 + hf], a_l[mt],
                                 b_h[hf * 2], b_h[hf * 2 + 1]);
            }
        }
        __syncthreads();
    }

    // ---- epilogue ----
    const int rbase = wm * 32 + (lane >> 2);
    const int cbase = wn * 64 + (lane & 3) * 2;
    if (pvmode) {
        const size_t orow0 = (size_t)(z >> 4) * 1024 + m0;
        const int ocol0 = (z & 15) * 256 + n0;
        #pragma unroll
        for (int mt = 0; mt < 2; mt++) {
            #pragma unroll
            for (int nt = 0; nt < 8; nt++) {
                #pragma unroll
                for (int hrow = 0; hrow < 2; hrow++) {
                    const size_t r = orow0 + rbase + mt * 16 + hrow * 8;
                    const int cc = ocol0 + cbase + nt * 8;
                    __nv_bfloat16 h[2], l[2];
                    split_bf16(acc[mt][nt][hrow * 2]     * alpha, h[0], l[0]);
                    split_bf16(acc[mt][nt][hrow * 2 + 1] * alpha, h[1], l[1]);
                    *(uint32_t*)(Oh + r * 4096 + cc) = *(const uint32_t*)h;
                    *(uint32_t*)(Ol + r * 4096 + cc) = *(const uint32_t*)l;
                }
            }
        }
    } else {
        float* C = Cp + (size_t)z * strideC;
        #pragma unroll
        for (int mt = 0; mt < 2; mt++) {
            #pragma unroll
            for (int nt = 0; nt < 8; nt++) {
                const int r0 = m0 + rbase + mt * 16;
                const int cc = n0 + cbase + nt * 8;
                float2 v0 = { acc[mt][nt][0] * alpha, acc[mt][nt][1] * alpha };
                float2 v1 = { acc[mt][nt][2] * alpha, acc[mt][nt][3] * alpha };
                *(float2*)(C + (size_t)r0 * ldc + cc)       = v0;
                *(float2*)(C + (size_t)(r0 + 8) * ldc + cc) = v1;
            }
        }
    }
}

// ===========================================================================
// Conversion / elementwise kernels
// ===========================================================================
__global__ void k_cvt(const float* __restrict__ x,
                      __nv_bfloat16* __restrict__ hi, __nv_bfloat16* __restrict__ lo)
{
    const size_t i = (size_t)blockIdx.x * 256 + threadIdx.x;
    const float4 v = ((const float4*)x)[i];
    __nv_bfloat16 h[4], l[4];
    split_bf16(v.x, h[0], l[0]); split_bf16(v.y, h[1], l[1]);
    split_bf16(v.z, h[2], l[2]); split_bf16(v.w, h[3], l[3]);
    ((uint2*)hi)[i] = *(const uint2*)h;
    ((uint2*)lo)[i] = *(const uint2*)l;
}

__global__ void k_cvt_t(const float* __restrict__ w,
                        __nv_bfloat16* __restrict__ hi, __nv_bfloat16* __restrict__ lo,
                        int R, int Cc)
{
    __shared__ float t[32][33];
    const int c0 = blockIdx.x * 32, r0 = blockIdx.y * 32;
    const int tx = threadIdx.x, ty = threadIdx.y;
    #pragma unroll
    for (int i = ty; i < 32; i += 8)
        t[i][tx] = w[(size_t)(r0 + i) * Cc + c0 + tx];
    __syncthreads();
    #pragma unroll
    for (int i = ty; i < 32; i += 8) {
        const float v = t[tx][i];
        __nv_bfloat16 h, l; split_bf16(v, h, l);
        const size_t o = (size_t)(c0 + i) * R + r0 + tx;
        hi[o] = h; lo[o] = l;
    }
}

__global__ void k_ropec(const int* __restrict__ pos_ids, const float* __restrict__ qkv,
                        __nv_bfloat16* __restrict__ Qh, __nv_bfloat16* __restrict__ Ql,
                        __nv_bfloat16* __restrict__ Kh, __nv_bfloat16* __restrict__ Kl)
{
    const int idx = blockIdx.x * 256 + threadIdx.x;
    const int j = idx & 127;
    const int h = (idx >> 7) & 15;
    const int tok = idx >> 11;
    const size_t src = (size_t)tok * 12288 + (size_t)h * 256;
    const size_t dst = (((size_t)(tok >> 10) * 16 + h) * 1024 + (tok & 1023)) * 256;

    if (j < 64) {
        const float pos = (float)pos_ids[tok];
        const float inv = exp2f(-13.287712379549449f * (float)j * (1.0f / 64.0f));
        float sn, cs; sincosf(pos * inv, &sn, &cs);
        const float qx1 = qkv[src + j], qx2 = qkv[src + j + 64];
        const float kx1 = qkv[src + 4096 + j], kx2 = qkv[src + 4096 + j + 64];
        __nv_bfloat16 h0, l0;
        split_bf16(qx1 * cs - qx2 * sn, h0, l0); Qh[dst + j] = h0;      Ql[dst + j] = l0;
        split_bf16(qx2 * cs + qx1 * sn, h0, l0); Qh[dst + j + 64] = h0; Ql[dst + j + 64] = l0;
        split_bf16(kx1 * cs - kx2 * sn, h0, l0); Kh[dst + j] = h0;      Kl[dst + j] = l0;
        split_bf16(kx2 * cs + kx1 * sn, h0, l0); Kh[dst + j + 64] = h0; Kl[dst + j + 64] = l0;
    } else {
        const int d1 = j + 64, d2 = j + 128;
        __nv_bfloat16 h0, l0;
        split_bf16(qkv[src + d1], h0, l0); Qh[dst + d1] = h0; Ql[dst + d1] = l0;
        split_bf16(qkv[src + d2], h0, l0); Qh[dst + d2] = h0; Ql[dst + d2] = l0;
        split_bf16(qkv[src + 4096 + d1], h0, l0); Kh[dst + d1] = h0; Kl[dst + d1] = l0;
        split_bf16(qkv[src + 4096 + d2], h0, l0); Kh[dst + d2] = h0; Kl[dst + d2] = l0;
    }
}

__global__ void k_vt(const float* __restrict__ qkv,
                     __nv_bfloat16* __restrict__ Vh, __nv_bfloat16* __restrict__ Vl)
{
    __shared__ float t[32][33];
    const int bh = blockIdx.z, b = bh >> 4, h = bh & 15;
    const int d0 = blockIdx.x * 32, s0 = blockIdx.y * 32;
    const int tx = threadIdx.x, ty = threadIdx.y;
    #pragma unroll
    for (int i = ty; i < 32; i += 8)
        t[i][tx] = qkv[((size_t)b * 1024 + s0 + i) * 12288 + 8192 + (size_t)h * 256 + d0 + tx];
    __syncthreads();
    #pragma unroll
    for (int i = ty; i < 32; i += 8) {
        const float v = t[tx][i];
        __nv_bfloat16 hh, ll; split_bf16(v, hh, ll);
        const size_t o = ((size_t)bh * 256 + d0 + i) * 1024 + s0 + tx;
        Vh[o] = hh; Vl[o] = ll;
    }
}

__global__ void k_softmax_cvt(const float* __restrict__ s,
                              __nv_bfloat16* __restrict__ Ph, __nv_bfloat16* __restrict__ Pl)
{
    __shared__ float redm[8], reds[8];
    const int row = blockIdx.x & 1023;
    const float* p = s + (size_t)blockIdx.x * 1024;
    const int tid = threadIdx.x;
    const int j0 = tid * 4;

    // read cap: cols past the row are masked anyway -> never load them
    float4 v;
    if (j0 <= row) {
        v = ((const float4*)p)[tid];
        if (j0 + 1 > row) v.y = -1e30f;
        if (j0 + 2 > row) v.z = -1e30f;
        if (j0 + 3 > row) v.w = -1e30f;
    } else {
        v = make_float4(-1e30f, -1e30f, -1e30f, -1e30f);
    }

    float m = fmaxf(fmaxf(v.x, v.y), fmaxf(v.z, v.w));
    #pragma unroll
    for (int o = 16; o; o >>= 1) m = fmaxf(m, __shfl_xor_sync(~0u, m, o));
    if ((tid & 31) == 0) redm[tid >> 5] = m;
    __syncthreads();
    m = redm[0];
    #pragma unroll
    for (int i = 1; i < 8; i++) m = fmaxf(m, redm[i]);

    const float e0 = __expf(v.x - m), e1 = __expf(v.y - m);
    const float e2 = __expf(v.z - m), e3 = __expf(v.w - m);
    float sl = (e0 + e1) + (e2 + e3);
    #pragma unroll
    for (int o = 16; o; o >>= 1) sl += __shfl_xor_sync(~0u, sl, o);
    if ((tid & 31) == 0) reds[tid >> 5] = sl;
    __syncthreads();
    float tot = reds[0];
    #pragma unroll
    for (int i = 1; i < 8; i++) tot += reds[i];

    // store cap: PV's K-cap reads only cols < (row|127)+1
    if (j0 <= (row | 127)) {
        const float inv = 1.0f / tot;
        __nv_bfloat16 h[4], l[4];
        split_bf16(e0 * inv, h[0], l[0]); split_bf16(e1 * inv, h[1], l[1]);
        split_bf16(e2 * inv, h[2], l[2]); split_bf16(e3 * inv, h[3], l[3]);
        const size_t o = (size_t)blockIdx.x * 256 + tid;
        ((uint2*)Ph)[o] = *(const uint2*)h;
        ((uint2*)Pl)[o] = *(const uint2*)l;
    }
}

// ===========================================================================
// Launch
// ===========================================================================
extern "C" void kernel_launch(void* const* d_in, const int* in_sizes, int n_in,
                              void* d_out, int out_size)
{
    const int*   pos  = (const int*)d_in[0];
    const float* hid  = (const float*)d_in[1];
    const float* wqkv = (const float*)d_in[2];
    const float* wout = (const float*)d_in[3];
    float* out = (float*)d_out;

    float *qkv, *scores;
    __nv_bfloat16 *Xh, *Xl, *WqTh, *WqTl, *WoTh, *WoTl;
    __nv_bfloat16 *Qh, *Ql, *Kh, *Kl, *Vth, *Vtl, *Ph, *Pl, *Ah, *Al;
    cudaGetSymbolAddress((void**)&qkv, g_qkv);
    cudaGetSymbolAddress((void**)&scores, g_scores);
    cudaGetSymbolAddress((void**)&Xh, g_Xh);   cudaGetSymbolAddress((void**)&Xl, g_Xl);
    cudaGetSymbolAddress((void**)&WqTh, g_WqTh); cudaGetSymbolAddress((void**)&WqTl, g_WqTl);
    cudaGetSymbolAddress((void**)&WoTh, g_WoTh); cudaGetSymbolAddress((void**)&WoTl, g_WoTl);
    cudaGetSymbolAddress((void**)&Qh, g_Qh);   cudaGetSymbolAddress((void**)&Ql, g_Ql);
    cudaGetSymbolAddress((void**)&Kh, g_Kh);   cudaGetSymbolAddress((void**)&Kl, g_Kl);
    cudaGetSymbolAddress((void**)&Vth, g_Vth); cudaGetSymbolAddress((void**)&Vtl, g_Vtl);
    cudaGetSymbolAddress((void**)&Ph, g_Ph);   cudaGetSymbolAddress((void**)&Pl, g_Pl);
    cudaGetSymbolAddress((void**)&Ah, g_Ah);   cudaGetSymbolAddress((void**)&Al, g_Al);

    cudaFuncSetAttribute(k_mma, cudaFuncAttributeMaxDynamicSharedMemorySize, SMEMSZ);

    // 1) operand conversions
    k_cvt<<<16384, 256>>>(hid, Xh, Xl);
    k_cvt_t<<<dim3(12288 / 32, 4096 / 32), dim3(32, 8)>>>(wqkv, WqTh, WqTl, 4096, 12288);
    k_cvt_t<<<dim3(4096 / 32, 4096 / 32), dim3(32, 8)>>>(wout, WoTh, WoTl, 4096, 4096);

    // 2) qkv = X @ Wqkv
    k_mma<<<dim3(96, 32, 1), 256, SMEMSZ>>>(Xh, Xl, WqTh, WqTl, qkv, nullptr, nullptr,
        4096, 4096, 4096, 12288, 0, 0, 0, 1.0f, 0, 0);

    // 3) RoPE(q,k) + V transpose
    k_ropec<<<32768, 256>>>(pos, qkv, Qh, Ql, Kh, Kl);
    k_vt<<<dim3(8, 32, 64), dim3(32, 8)>>>(qkv, Vth, Vtl);

    // 4) scores = scale * Q @ K^T, causal tile skip
    k_mma<<<dim3(8, 8, 64), 256, SMEMSZ>>>(Qh, Ql, Kh, Kl, scores, nullptr, nullptr,
        256, 256, 256, 1024, 1024 * 256, 1024 * 256, 1024 * 1024, 0.0625f, 1, 0);

    // 5) softmax -> bf16 hi/lo probs (read+store capped at causal bounds)
    k_softmax_cvt<<<64 * 1024, 256>>>(scores, Ph, Pl);

    // 6) attn = P @ V, causal K-cap, epilogue emits bf16 hi/lo (Ah/Al)
    k_mma<<<dim3(2, 8, 64), 256, SMEMSZ>>>(Ph, Pl, Vth, Vtl, nullptr, Ah, Al,
        1024, 1024, 1024, 4096, 1024 * 1024, 256 * 1024, 0, 1.0f, 2, 1);

    // 7) out = attn @ Wout
    k_mma<<<dim3(32, 32, 1), 256, SMEMSZ>>>(Ah, Al, WoTh, WoTl, out, nullptr, nullptr,
        4096, 4096, 4096, 4096, 0, 0, 0, 1.0f, 0, 0);
}